// round 1
// baseline (speedup 1.0000x reference)
#include <cuda_runtime.h>

// PINN_Difference_RNN: x_t = W_A x_{t-1} + b_A + W_B u_t + b_B
//                      out_t = (x_{t-1} + c*[cos(th), sin(th)]) - x_t,
//                      c = u0_t * dt_t, th = u1_t.
// Constant contractive A => chunked recurrence with warm-up from zero state.

#define T_TOTAL   4194304
#define L_CHUNK   128            // output steps per thread (chunk length)
#define W_WARM    64             // warm-up steps (A^64 ~ 0)
#define NTH       128            // threads per CTA
#define TS        16             // timeline steps per smem tile
#define RUN       (W_WARM + L_CHUNK)   // 192
#define NTILES    (RUN / TS)           // 12
#define WARMTILES (W_WARM / TS)        // 4
#define NCHUNK    (T_TOTAL / L_CHUNK)  // 32768
#define NBLK      (NCHUNK / NTH)       // 256
#define PAD       (NTH + 2)            // 130 -> conflict-free transposed tiles

__global__ __launch_bounds__(NTH) void pinn_rnn_kernel(
    const float* __restrict__ x0p,
    const float* __restrict__ u,     // [2, T] row-major: u0 at [t], u1 at [T+t]
    const float* __restrict__ td,    // [T]
    const float* __restrict__ WA,    // [2,2] row-major
    const float* __restrict__ bA,
    const float* __restrict__ WB,
    const float* __restrict__ bB,
    float2* __restrict__ out)        // [T] pairs
{
    __shared__ float s_u0[TS][PAD];
    __shared__ float s_u1[TS][PAD];
    __shared__ float s_dt[TS][PAD];
    __shared__ float s_ox[TS][PAD];
    __shared__ float s_oy[TS][PAD];

    const int tid = threadIdx.x;
    const int blk = blockIdx.x;

    // Scalar parameters (L1/L2-cached broadcast loads)
    const float a00 = WA[0], a01 = WA[1], a10 = WA[2], a11 = WA[3];
    const float w00 = WB[0], w01 = WB[1], w10 = WB[2], w11 = WB[3];
    const float cb0 = bA[0] + bB[0];
    const float cb1 = bA[1] + bB[1];

    const int chunk = blk * NTH + tid;
    // time index of run position 0 for local run r of this CTA:
    //   g(r, p) = blk*NTH*L + r*L - W + p
    const int seg_base = blk * NTH * L_CHUNK - W_WARM;

    // state = x_{g-1}; chunk 0 uses exact x_0, others warm up from 0
    float xs0, xs1;
    if (chunk == 0) { xs0 = x0p[0]; xs1 = x0p[1]; }
    else            { xs0 = 0.0f;   xs1 = 0.0f;  }

    // ---- warm-up tiles (no output) ----
    for (int k = 0; k < WARMTILES; ++k) {
        const int base_k = seg_base + k * TS;
        #pragma unroll
        for (int p = 0; p < TS; ++p) {
            int idx = p * NTH + tid;
            int r = idx >> 4;           // idx / TS
            int j = idx & (TS - 1);
            int g = base_k + r * L_CHUNK + j;
            int gs = g < 0 ? 0 : g;     // only CTA 0 / run 0 ever negative
            s_u0[j][r] = u[gs];
            s_u1[j][r] = u[T_TOTAL + gs];
            s_dt[j][r] = td[gs];
        }
        __syncthreads();
        if (chunk != 0) {               // chunk 0: all warm steps have g<0 -> keep x_0
            #pragma unroll
            for (int j = 0; j < TS; ++j) {
                float u0v = s_u0[j][tid];
                float u1v = s_u1[j][tid];
                float f0 = fmaf(w00, u0v, fmaf(w01, u1v, cb0));
                float f1 = fmaf(w10, u0v, fmaf(w11, u1v, cb1));
                float n0 = fmaf(a00, xs0, fmaf(a01, xs1, f0));
                float n1 = fmaf(a10, xs0, fmaf(a11, xs1, f1));
                xs0 = n0; xs1 = n1;
            }
        }
        __syncthreads();
    }

    // ---- output tiles ----
    for (int k = WARMTILES; k < NTILES; ++k) {
        const int base_k = seg_base + k * TS;
        #pragma unroll
        for (int p = 0; p < TS; ++p) {
            int idx = p * NTH + tid;
            int r = idx >> 4;
            int j = idx & (TS - 1);
            int g = base_k + r * L_CHUNK + j;   // >= 0 here for all runs
            s_u0[j][r] = u[g];
            s_u1[j][r] = u[T_TOTAL + g];
            s_dt[j][r] = td[g];
        }
        __syncthreads();
        #pragma unroll
        for (int j = 0; j < TS; ++j) {
            float u0v = s_u0[j][tid];
            float u1v = s_u1[j][tid];
            float dtv = s_dt[j][tid];
            float f0 = fmaf(w00, u0v, fmaf(w01, u1v, cb0));
            float f1 = fmaf(w10, u0v, fmaf(w11, u1v, cb1));
            float n0 = fmaf(a00, xs0, fmaf(a01, xs1, f0));
            float n1 = fmaf(a10, xs0, fmaf(a11, xs1, f1));
            float c = u0v * dtv;
            float sn, cs;
            __sincosf(u1v, &sn, &cs);
            s_ox[j][tid] = fmaf(c, cs, xs0) - n0;
            s_oy[j][tid] = fmaf(c, sn, xs1) - n1;
            xs0 = n0; xs1 = n1;
        }
        __syncthreads();
        #pragma unroll
        for (int p = 0; p < TS; ++p) {
            int idx = p * NTH + tid;
            int r = idx >> 4;
            int j = idx & (TS - 1);
            int g = base_k + r * L_CHUNK + j;
            out[g] = make_float2(s_ox[j][r], s_oy[j][r]);
        }
        // no sync needed here: next tile's loads touch s_u* only, and the
        // sync after that load protects s_ox/s_oy against tile k+1 staging
    }
}

extern "C" void kernel_launch(void* const* d_in, const int* in_sizes, int n_in,
                              void* d_out, int out_size) {
    const float* x0 = (const float*)d_in[0];
    const float* u  = (const float*)d_in[1];
    const float* td = (const float*)d_in[2];
    const float* WA = (const float*)d_in[3];
    const float* bA = (const float*)d_in[4];
    const float* WB = (const float*)d_in[5];
    const float* bB = (const float*)d_in[6];
    float2* out = (float2*)d_out;

    pinn_rnn_kernel<<<NBLK, NTH>>>(x0, u, td, WA, bA, WB, bB, out);
}

// round 3
// speedup vs baseline: 1.0969x; 1.0969x over previous
#include <cuda_runtime.h>

// PINN_Difference_RNN: x_t = W_A x_{t-1} + b_A + W_B u_t + b_B
//                      out_t = (x_{t-1} + c*[cos(th), sin(th)]) - x_t,
//                      c = u0_t * dt_t, th = u1_t.
// Constant contractive A => chunked recurrence with warm-up from zero state.
// R3 == R2 resubmit (container infra failure, no data): L=64/W=48, 65536 threads.

#define T_TOTAL   4194304
#define L_CHUNK   64             // output steps per thread (chunk length)
#define W_WARM    48             // warm-up steps (rho^48 ~ 6e-6 rel, safe vs 1e-3)
#define NTH       128            // threads per CTA
#define TS        16             // timeline steps per smem tile
#define RUN       (W_WARM + L_CHUNK)   // 112
#define NTILES    (RUN / TS)           // 7
#define WARMTILES (W_WARM / TS)        // 3
#define NCHUNK    (T_TOTAL / L_CHUNK)  // 65536
#define NBLK      (NCHUNK / NTH)       // 512
#define PAD       (NTH + 2)            // 130 -> conflict-free transposed tiles

__global__ __launch_bounds__(NTH) void pinn_rnn_kernel(
    const float* __restrict__ x0p,
    const float* __restrict__ u,     // [2, T] row-major: u0 at [t], u1 at [T+t]
    const float* __restrict__ td,    // [T]
    const float* __restrict__ WA,    // [2,2] row-major
    const float* __restrict__ bA,
    const float* __restrict__ WB,
    const float* __restrict__ bB,
    float2* __restrict__ out)        // [T] pairs
{
    __shared__ float s_u0[TS][PAD];
    __shared__ float s_u1[TS][PAD];
    __shared__ float s_dt[TS][PAD];
    __shared__ float s_ox[TS][PAD];
    __shared__ float s_oy[TS][PAD];

    const int tid = threadIdx.x;
    const int blk = blockIdx.x;

    // Scalar parameters (L1/L2-cached broadcast loads)
    const float a00 = WA[0], a01 = WA[1], a10 = WA[2], a11 = WA[3];
    const float w00 = WB[0], w01 = WB[1], w10 = WB[2], w11 = WB[3];
    const float cb0 = bA[0] + bB[0];
    const float cb1 = bA[1] + bB[1];

    const int chunk = blk * NTH + tid;
    // time index of run position 0 for local run r of this CTA:
    //   g(r, p) = blk*NTH*L + r*L - W + p
    const int seg_base = blk * NTH * L_CHUNK - W_WARM;

    // state = x_{g-1}; chunk 0 uses exact x_0, others warm up from 0
    float xs0, xs1;
    if (chunk == 0) { xs0 = x0p[0]; xs1 = x0p[1]; }
    else            { xs0 = 0.0f;   xs1 = 0.0f;  }

    // ---- warm-up tiles (no output) ----
    for (int k = 0; k < WARMTILES; ++k) {
        const int base_k = seg_base + k * TS;
        #pragma unroll
        for (int p = 0; p < TS; ++p) {
            int idx = p * NTH + tid;
            int r = idx >> 4;           // idx / TS
            int j = idx & (TS - 1);
            int g = base_k + r * L_CHUNK + j;
            int gs = g < 0 ? 0 : g;     // only CTA 0 / run 0 ever negative
            s_u0[j][r] = u[gs];
            s_u1[j][r] = u[T_TOTAL + gs];
            s_dt[j][r] = td[gs];
        }
        __syncthreads();
        if (chunk != 0) {               // chunk 0: all warm steps have g<0 -> keep x_0
            #pragma unroll
            for (int j = 0; j < TS; ++j) {
                float u0v = s_u0[j][tid];
                float u1v = s_u1[j][tid];
                float f0 = fmaf(w00, u0v, fmaf(w01, u1v, cb0));
                float f1 = fmaf(w10, u0v, fmaf(w11, u1v, cb1));
                float n0 = fmaf(a00, xs0, fmaf(a01, xs1, f0));
                float n1 = fmaf(a10, xs0, fmaf(a11, xs1, f1));
                xs0 = n0; xs1 = n1;
            }
        }
        __syncthreads();
    }

    // ---- output tiles ----
    for (int k = WARMTILES; k < NTILES; ++k) {
        const int base_k = seg_base + k * TS;
        #pragma unroll
        for (int p = 0; p < TS; ++p) {
            int idx = p * NTH + tid;
            int r = idx >> 4;
            int j = idx & (TS - 1);
            int g = base_k + r * L_CHUNK + j;   // >= 0 here for all runs
            s_u0[j][r] = u[g];
            s_u1[j][r] = u[T_TOTAL + g];
            s_dt[j][r] = td[g];
        }
        __syncthreads();
        #pragma unroll
        for (int j = 0; j < TS; ++j) {
            float u0v = s_u0[j][tid];
            float u1v = s_u1[j][tid];
            float dtv = s_dt[j][tid];
            float f0 = fmaf(w00, u0v, fmaf(w01, u1v, cb0));
            float f1 = fmaf(w10, u0v, fmaf(w11, u1v, cb1));
            float n0 = fmaf(a00, xs0, fmaf(a01, xs1, f0));
            float n1 = fmaf(a10, xs0, fmaf(a11, xs1, f1));
            float c = u0v * dtv;
            float sn, cs;
            __sincosf(u1v, &sn, &cs);
            s_ox[j][tid] = fmaf(c, cs, xs0) - n0;
            s_oy[j][tid] = fmaf(c, sn, xs1) - n1;
            xs0 = n0; xs1 = n1;
        }
        __syncthreads();
        #pragma unroll
        for (int p = 0; p < TS; ++p) {
            int idx = p * NTH + tid;
            int r = idx >> 4;
            int j = idx & (TS - 1);
            int g = base_k + r * L_CHUNK + j;
            out[g] = make_float2(s_ox[j][r], s_oy[j][r]);
        }
        // no sync needed here: next tile's loads touch s_u* only, and the
        // sync after that load protects s_ox/s_oy against tile k+1 staging
    }
}

extern "C" void kernel_launch(void* const* d_in, const int* in_sizes, int n_in,
                              void* d_out, int out_size) {
    const float* x0 = (const float*)d_in[0];
    const float* u  = (const float*)d_in[1];
    const float* td = (const float*)d_in[2];
    const float* WA = (const float*)d_in[3];
    const float* bA = (const float*)d_in[4];
    const float* WB = (const float*)d_in[5];
    const float* bB = (const float*)d_in[6];
    float2* out = (float2*)d_out;

    pinn_rnn_kernel<<<NBLK, NTH>>>(x0, u, td, WA, bA, WB, bB, out);
}